// round 1
// baseline (speedup 1.0000x reference)
#include <cuda_runtime.h>
#include <cuda_bf16.h>
#include <cstdint>

// ---------------------------------------------------------------------------
// ArcFace loss, fused:
//   k_norm_x : normalize x rows, store bf16
//   k_main   : GEMM (Xn @ Wn^T) with fused per-row sum of exp(64*cos - 64),
//              per-chunk partials + target-cos capture (fixed-max LSE trick)
//   k_final  : combine partials, apply margin at target, CE, mean
// ---------------------------------------------------------------------------

namespace {
constexpr int NUM_C = 100000;
constexpr int DIM   = 512;
constexpr int NB    = 512;

constexpr int MT    = 128;           // rows per CTA (M tile)
constexpr int NT    = 64;            // classes per subtile
constexpr int NSUB  = 43;            // subtiles per chunk
constexpr int CHUNK = NSUB * NT;     // 2752 classes per CTA
constexpr int GCH   = 37;            // 37*2752 = 101824 >= 100000; grid = 4x37 = 148 CTAs

constexpr int XS    = DIM + 8;       // padded bf16 row stride (conflict-free LDS)
constexpr int WS    = DIM + 8;

constexpr float COS_M = 0.8775825618903728f;   // cos(0.5)
constexpr float SIN_M = 0.479425538604203f;    // sin(0.5)
constexpr float TH    = -0.8775825618903728f;  // -cos(m)
constexpr float MMRG  = 0.2397127693021015f;   // sin(m)*m

constexpr size_t SMEM_BYTES =
    (size_t)MT * XS * 2 +   // x tile bf16
    (size_t)NT * WS * 2 +   // w tile bf16
    (size_t)NT * 4 +        // w inv norms
    (size_t)MT * 2 * 4 +    // row accumulators [row][wn]
    (size_t)MT * 4;         // y tile
} // namespace

__device__ __align__(16) __nv_bfloat16 g_xn[NB * DIM];
__device__ float g_tgt[NB];
__device__ float g_partial[GCH * NB];

// ---------------------------------------------------------------------------
__global__ void k_norm_x(const float* __restrict__ x) {
    int row  = blockIdx.x * 8 + (threadIdx.x >> 5);   // grid 64 x 256 -> 512 rows
    int lane = threadIdx.x & 31;
    const float* xr = x + (size_t)row * DIM;
    float s = 0.f;
    #pragma unroll
    for (int i = lane; i < DIM; i += 32) { float v = xr[i]; s += v * v; }
    #pragma unroll
    for (int o = 16; o; o >>= 1) s += __shfl_xor_sync(0xFFFFFFFFu, s, o);
    float inv = rsqrtf(fmaxf(s, 1e-24f));
    #pragma unroll
    for (int i = lane; i < DIM; i += 32)
        g_xn[(size_t)row * DIM + i] = __float2bfloat16(xr[i] * inv);
}

// ---------------------------------------------------------------------------
__device__ __forceinline__ void mma16816(float* c, const uint32_t* a, const uint32_t* b) {
    asm volatile(
        "mma.sync.aligned.m16n8k16.row.col.f32.bf16.bf16.f32 "
        "{%0,%1,%2,%3}, {%4,%5,%6,%7}, {%8,%9}, {%0,%1,%2,%3};\n"
        : "+f"(c[0]), "+f"(c[1]), "+f"(c[2]), "+f"(c[3])
        : "r"(a[0]), "r"(a[1]), "r"(a[2]), "r"(a[3]), "r"(b[0]), "r"(b[1]));
}

__global__ void __launch_bounds__(256, 1)
k_main(const float* __restrict__ w, const int* __restrict__ y) {
    extern __shared__ char smem[];
    __nv_bfloat16* x_s   = (__nv_bfloat16*)smem;                 // MT*XS
    __nv_bfloat16* w_s   = x_s + MT * XS;                        // NT*WS
    float*         winv  = (float*)(w_s + NT * WS);              // NT
    float*         racc  = winv + NT;                            // MT*2
    int*           y_s   = (int*)(racc + MT * 2);                // MT

    const int mb    = blockIdx.x * MT;
    const int cbase = blockIdx.y * CHUNK;
    const int tid   = threadIdx.x;

    // --- load x tile (pre-normalized bf16) into padded smem ---
    {
        const uint32_t* xn32 = (const uint32_t*)g_xn;
        for (int i = tid; i < MT * (DIM / 2); i += 256) {
            int r = i / (DIM / 2), c2 = i % (DIM / 2);
            *(uint32_t*)&x_s[r * XS + c2 * 2] = xn32[(size_t)(mb + r) * (DIM / 2) + c2];
        }
    }
    if (tid < MT) y_s[tid] = y[mb + tid];
    for (int i = tid; i < MT * 2; i += 256) racc[i] = 0.f;

    const int wid = tid >> 5, lane = tid & 31;
    const int wm = wid & 3, wn = wid >> 2;   // 4 x 2 warp grid (M x N)
    const int g = lane >> 2, q = lane & 3;

    __syncthreads();

    for (int sub = 0; sub < NSUB; ++sub) {
        const int c0 = cbase + sub * NT;

        // --- load W subtile fp32 -> bf16 into padded smem (zero-pad OOB) ---
        for (int i = tid; i < NT * (DIM / 2); i += 256) {
            int r = i / (DIM / 2), c2 = i % (DIM / 2);
            int cls = c0 + r;
            uint32_t v = 0;
            if (cls < NUM_C) {
                float2 f = *(const float2*)&w[(size_t)cls * DIM + c2 * 2];
                __nv_bfloat162 h = __floats2bfloat162_rn(f.x, f.y);
                v = *(uint32_t*)&h;
            }
            *(uint32_t*)&w_s[r * WS + c2 * 2] = v;
        }
        __syncthreads();

        // --- per-row inverse norms of W subtile (each warp: 8 rows) ---
        #pragma unroll
        for (int rr = 0; rr < 8; ++rr) {
            int r = wid * 8 + rr;
            float s = 0.f;
            const uint32_t* wr = (const uint32_t*)&w_s[r * WS];
            #pragma unroll
            for (int i = lane; i < DIM / 2; i += 32) {
                __nv_bfloat162 h = *(const __nv_bfloat162*)&wr[i];
                float a = __bfloat162float(h.x), b = __bfloat162float(h.y);
                s += a * a + b * b;
            }
            #pragma unroll
            for (int o = 16; o; o >>= 1) s += __shfl_xor_sync(0xFFFFFFFFu, s, o);
            if (lane == 0) winv[r] = (c0 + r < NUM_C) ? rsqrtf(s) : 0.f;
        }
        __syncthreads();

        // --- MMA: warp tile 32x32, K = 512 ---
        float acc[2][4][4];
        #pragma unroll
        for (int mi = 0; mi < 2; mi++)
            #pragma unroll
            for (int ni = 0; ni < 4; ni++)
                #pragma unroll
                for (int j = 0; j < 4; j++) acc[mi][ni][j] = 0.f;

        const __nv_bfloat16* xa = x_s + (wm * 32 + g) * XS + q * 2;
        const __nv_bfloat16* wb = w_s + (wn * 32 + g) * WS + q * 2;

        #pragma unroll
        for (int k0 = 0; k0 < DIM; k0 += 16) {
            uint32_t a[2][4], b[4][2];
            #pragma unroll
            for (int mi = 0; mi < 2; mi++) {
                const __nv_bfloat16* p = xa + mi * (16 * XS) + k0;
                a[mi][0] = *(const uint32_t*)(p);
                a[mi][1] = *(const uint32_t*)(p + 8 * XS);
                a[mi][2] = *(const uint32_t*)(p + 8);
                a[mi][3] = *(const uint32_t*)(p + 8 * XS + 8);
            }
            #pragma unroll
            for (int ni = 0; ni < 4; ni++) {
                const __nv_bfloat16* p = wb + ni * (8 * WS) + k0;
                b[ni][0] = *(const uint32_t*)(p);
                b[ni][1] = *(const uint32_t*)(p + 8);
            }
            #pragma unroll
            for (int mi = 0; mi < 2; mi++)
                #pragma unroll
                for (int ni = 0; ni < 4; ni++)
                    mma16816(acc[mi][ni], a[mi], b[ni]);
        }

        // --- epilogue: cos = acc * winv; accumulate exp(64*cos - 64) per row ---
        #pragma unroll
        for (int mi = 0; mi < 2; mi++) {
            float rs[2] = {0.f, 0.f};
            #pragma unroll
            for (int ni = 0; ni < 4; ni++) {
                #pragma unroll
                for (int j = 0; j < 4; j++) {
                    int rl  = wm * 32 + mi * 16 + g + (j >> 1) * 8;
                    int cl  = wn * 32 + ni * 8 + q * 2 + (j & 1);
                    int cls = c0 + cl;
                    float cosv = acc[mi][ni][j] * winv[cl];
                    if (cls == y_s[rl]) g_tgt[mb + rl] = cosv;
                    float e = (cls < NUM_C) ? __expf(cosv * 64.f - 64.f) : 0.f;
                    rs[j >> 1] += e;
                }
            }
            #pragma unroll
            for (int h = 0; h < 2; h++) {
                float v = rs[h];
                v += __shfl_xor_sync(0xFFFFFFFFu, v, 1);
                v += __shfl_xor_sync(0xFFFFFFFFu, v, 2);
                if (q == 0)
                    racc[(wm * 32 + mi * 16 + g + h * 8) * 2 + wn] += v;
            }
        }
        __syncthreads();
    }

    // --- write per-chunk row partials (deterministic, single writer) ---
    for (int r = tid; r < MT; r += 256)
        g_partial[(size_t)blockIdx.y * NB + mb + r] = racc[r * 2] + racc[r * 2 + 1];
}

// ---------------------------------------------------------------------------
__global__ void k_final(float* __restrict__ out) {
    __shared__ float red[NB];
    int b = threadIdx.x;
    float S = 0.f;
    for (int c = 0; c < GCH; ++c) S += g_partial[(size_t)c * NB + b];

    float ct  = g_tgt[b];
    float sn  = sqrtf(fmaxf(1.f - ct * ct, 0.f));
    float cwm = ct * COS_M - sn * SIN_M;
    float phi = (ct > TH) ? cwm : (ct - MMRG);
    // swap the target's plain term for the margin term (bitwise-identical expf arg)
    float Sp  = S - __expf(ct * 64.f - 64.f) + __expf(phi * 64.f - 64.f);
    float nll = 64.f + logf(Sp) - 64.f * phi;

    red[b] = nll;
    __syncthreads();
    #pragma unroll
    for (int s = 256; s; s >>= 1) {
        if (b < s) red[b] += red[b + s];
        __syncthreads();
    }
    if (b == 0) out[0] = red[0] / (float)NB;
}

// ---------------------------------------------------------------------------
extern "C" void kernel_launch(void* const* d_in, const int* in_sizes, int n_in,
                              void* d_out, int out_size) {
    const float* x = (const float*)d_in[0];
    const int*   y = (const int*)d_in[1];
    const float* w = (const float*)d_in[2];
    float* out = (float*)d_out;

    cudaFuncSetAttribute(k_main, cudaFuncAttributeMaxDynamicSharedMemorySize,
                         (int)SMEM_BYTES);

    k_norm_x<<<64, 256>>>(x);
    k_main<<<dim3(4, GCH), 256, SMEM_BYTES>>>(w, y);
    k_final<<<1, NB>>>(out);
}

// round 3
// speedup vs baseline: 2.8937x; 2.8937x over previous
#include <cuda_runtime.h>
#include <cuda_bf16.h>
#include <cstdint>

// ---------------------------------------------------------------------------
// ArcFace loss on GB300 (sm_103a). tcgen05 is rejected by this harness's
// compute_103 virtual target, so: best-effort mma.sync pipeline.
//   k_prep  : W fp32 -> bf16 (g_wn) + inv-norms (g_winv); X rows normalized
//             to bf16 (g_xn).
//   k_main  : 1564 CTAs (4 M-tiles x 391 chunks of 256 classes).
//             X tile (128x512 bf16) smem-resident; W streamed via 3-stage
//             cp.async pipeline; 64x64 warp tiles, ldmatrix.x4 + HMMA;
//             fused exp(64*cos-64) row sums (fixed-max LSE trick).
//   k_final : combine partials, margin at target, CE, mean.
// ---------------------------------------------------------------------------

namespace {
constexpr int NUM_C = 100000;
constexpr int DIM   = 512;
constexpr int NB    = 512;

constexpr int NPC   = 256;                        // classes per CTA
constexpr int NCCH  = (NUM_C + NPC - 1) / NPC;    // 391
constexpr int CPAD  = NCCH * NPC;                 // 100096

constexpr int SM_X  = 0;                // 8 chunks * 16384 = 131072
constexpr int SM_W  = 131072;           // 3 stages * 32768 = 98304
constexpr size_t SMEM_BYTES = 229376;   // <= 232448

constexpr float COS_M = 0.8775825618903728f;   // cos(0.5)
constexpr float SIN_M = 0.479425538604203f;    // sin(0.5)
constexpr float THv   = -0.8775825618903728f;  // -cos(m)
constexpr float MMRG  = 0.2397127693021015f;   // sin(m)*m
} // namespace

__device__ __align__(16) __nv_bfloat16 g_xn[NB * DIM];
__device__ __align__(16) __nv_bfloat16 g_wn[(size_t)CPAD * DIM];
__device__ float g_winv[CPAD];
__device__ float g_tgt[NB];
__device__ float g_partial[(size_t)NCCH * NB];

// ---------------------------------------------------------------------------
__device__ __forceinline__ uint32_t smem_u32(const void* p) {
    uint32_t a;
    asm("{ .reg .u64 t; cvta.to.shared.u64 t, %1; cvt.u32.u64 %0, t; }"
        : "=r"(a) : "l"(p));
    return a;
}
#define CP_ASYNC16(dst, src) \
    asm volatile("cp.async.cg.shared.global [%0], [%1], 16;" \
                 :: "r"(dst), "l"(src) : "memory")
#define CP_COMMIT() asm volatile("cp.async.commit_group;" ::: "memory")
#define CP_WAIT2()  asm volatile("cp.async.wait_group 2;" ::: "memory")

#define LDSM4(r, addr) \
    asm volatile("ldmatrix.sync.aligned.m8n8.x4.shared.b16 {%0,%1,%2,%3}, [%4];" \
                 : "=r"((r)[0]), "=r"((r)[1]), "=r"((r)[2]), "=r"((r)[3])        \
                 : "r"(addr))

__device__ __forceinline__ void mma16816(float* c, const uint32_t* a,
                                         const uint32_t* b) {
    asm volatile(
        "mma.sync.aligned.m16n8k16.row.col.f32.bf16.bf16.f32 "
        "{%0,%1,%2,%3}, {%4,%5,%6,%7}, {%8,%9}, {%0,%1,%2,%3};\n"
        : "+f"(c[0]), "+f"(c[1]), "+f"(c[2]), "+f"(c[3])
        : "r"(a[0]), "r"(a[1]), "r"(a[2]), "r"(a[3]), "r"(b[0]), "r"(b[1]));
}

// ---------------------------------------------------------------------------
// Prep: blocks 0..781 convert W rows (128 each, zero-padding past NUM_C);
//       blocks 782..783 normalize X rows (256 each).
// ---------------------------------------------------------------------------
__global__ void k_prep(const float* __restrict__ x, const float* __restrict__ w) {
    const int bid  = blockIdx.x;
    const int wid  = threadIdx.x >> 5;
    const int lane = threadIdx.x & 31;

    if (bid < CPAD / 128) {
        const int base = bid * 128 + wid * 16;
        for (int r = 0; r < 16; ++r) {
            const int row = base + r;
            float4 v[4];
            float ss = 0.f;
            if (row < NUM_C) {
                const float4* src = (const float4*)(w + (size_t)row * DIM);
                #pragma unroll
                for (int i = 0; i < 4; ++i) {
                    v[i] = src[lane + 32 * i];
                    ss += v[i].x * v[i].x + v[i].y * v[i].y
                        + v[i].z * v[i].z + v[i].w * v[i].w;
                }
            } else {
                #pragma unroll
                for (int i = 0; i < 4; ++i) v[i] = make_float4(0, 0, 0, 0);
            }
            #pragma unroll
            for (int o = 16; o; o >>= 1) ss += __shfl_xor_sync(0xFFFFFFFFu, ss, o);

            uint2* dst = (uint2*)(g_wn + (size_t)row * DIM);
            #pragma unroll
            for (int i = 0; i < 4; ++i) {
                __nv_bfloat162 lo = __floats2bfloat162_rn(v[i].x, v[i].y);
                __nv_bfloat162 hi = __floats2bfloat162_rn(v[i].z, v[i].w);
                uint2 u;
                u.x = *(uint32_t*)&lo;
                u.y = *(uint32_t*)&hi;
                dst[lane + 32 * i] = u;
            }
            if (lane == 0)
                g_winv[row] = (row < NUM_C) ? rsqrtf(fmaxf(ss, 1e-24f)) : 0.f;
        }
    } else {
        const int xb = (bid - CPAD / 128) * 256 + wid * 32;
        for (int r = 0; r < 32; ++r) {
            const int row = xb + r;
            const float4* xr = (const float4*)(x + (size_t)row * DIM);
            float4 v[4];
            float s = 0.f;
            #pragma unroll
            for (int j = 0; j < 4; ++j) {
                v[j] = xr[lane + 32 * j];
                s += v[j].x * v[j].x + v[j].y * v[j].y
                   + v[j].z * v[j].z + v[j].w * v[j].w;
            }
            #pragma unroll
            for (int o = 16; o; o >>= 1) s += __shfl_xor_sync(0xFFFFFFFFu, s, o);
            float inv = rsqrtf(fmaxf(s, 1e-24f));
            uint2* dst = (uint2*)(g_xn + (size_t)row * DIM);
            #pragma unroll
            for (int j = 0; j < 4; ++j) {
                __nv_bfloat162 lo = __floats2bfloat162_rn(v[j].x * inv, v[j].y * inv);
                __nv_bfloat162 hi = __floats2bfloat162_rn(v[j].z * inv, v[j].w * inv);
                uint2 u;
                u.x = *(uint32_t*)&lo;
                u.y = *(uint32_t*)&hi;
                dst[lane + 32 * j] = u;
            }
        }
    }
}

// ---------------------------------------------------------------------------
__global__ void __launch_bounds__(256, 1)
k_main(const int* __restrict__ y) {
    extern __shared__ char smem[];
    const uint32_t sb = smem_u32(smem);
    const int tid  = threadIdx.x;
    const int wid  = tid >> 5;
    const int lane = tid & 31;
    const int mt   = blockIdx.x;          // 0..3
    const int cch  = blockIdx.y;          // 0..390
    const int c0   = cch * NPC;
    const int wm   = wid >> 2;             // 0..1
    const int wn   = wid & 3;              // 0..3

    // ---- prologue: X tile (group 0) + first W stage (group 0), W1, W2 ----
    {
        const char* xsrc = (const char*)g_xn + (size_t)mt * 128 * DIM * 2;
        #pragma unroll
        for (int i = 0; i < 32; ++i) {
            int li  = tid + 256 * i;
            int c   = li >> 10, lc = li & 1023;
            int row = lc >> 3, seg = lc & 7;
            uint32_t dst = sb + SM_X + c * 16384 + row * 128
                         + ((seg * 16) ^ ((row & 7) << 4));
            const char* src = xsrc + ((size_t)row * DIM + c * 64 + seg * 8) * 2;
            CP_ASYNC16(dst, src);
        }
    }
    const char* wbase = (const char*)g_wn + (size_t)c0 * DIM * 2;
    #define ISSUE_W(kc) do {                                                  \
        uint32_t stg = sb + SM_W + ((kc) % 3) * 32768;                        \
        _Pragma("unroll")                                                     \
        for (int i = 0; i < 8; ++i) {                                         \
            int li = tid + 256 * i;                                           \
            int row = li >> 3, seg = li & 7;                                  \
            uint32_t dst = stg + row * 128 + ((seg * 16) ^ ((row & 7) << 4)); \
            const char* src = wbase + ((size_t)row * DIM + (kc) * 64 + seg * 8) * 2; \
            CP_ASYNC16(dst, src);                                             \
        }                                                                     \
    } while (0)

    ISSUE_W(0); CP_COMMIT();
    ISSUE_W(1); CP_COMMIT();
    ISSUE_W(2); CP_COMMIT();

    float acc[4][8][4];
    #pragma unroll
    for (int mi = 0; mi < 4; ++mi)
        #pragma unroll
        for (int ni = 0; ni < 8; ++ni)
            #pragma unroll
            for (int j = 0; j < 4; ++j) acc[mi][ni][j] = 0.f;

    const uint32_t swz      = (lane & 7) << 4;
    const uint32_t xrowbase = (wm * 64 + (lane & 15)) * 128;
    const uint32_t kxA      = (lane >> 4) << 4;
    const uint32_t browbase = (wn * 64 + (lane & 7) + ((lane >> 4) << 3)) * 128;
    const uint32_t kxB      = ((lane >> 3) & 1) << 4;

    for (int kc = 0; kc < 8; ++kc) {
        CP_WAIT2();
        __syncthreads();
        const uint32_t xch = sb + SM_X + kc * 16384 + xrowbase;
        const uint32_t wst = sb + SM_W + (kc % 3) * 32768 + browbase;
        #pragma unroll
        for (int ks = 0; ks < 4; ++ks) {
            uint32_t a[4][4], bq[4][4];
            const uint32_t ka = (uint32_t)(ks * 32 + kxA) ^ swz;
            const uint32_t kb = (uint32_t)(ks * 32 + kxB) ^ swz;
            #pragma unroll
            for (int mi = 0; mi < 4; ++mi) LDSM4(a[mi], xch + mi * 2048 + ka);
            #pragma unroll
            for (int nb = 0; nb < 4; ++nb) LDSM4(bq[nb], wst + nb * 2048 + kb);
            #pragma unroll
            for (int mi = 0; mi < 4; ++mi)
                #pragma unroll
                for (int nb = 0; nb < 4; ++nb) {
                    mma16816(acc[mi][2 * nb],     a[mi], &bq[nb][0]);
                    mma16816(acc[mi][2 * nb + 1], a[mi], &bq[nb][2]);
                }
        }
        __syncthreads();
        if (kc < 5) ISSUE_W(kc + 3);
        CP_COMMIT();
    }

    // ---- epilogue: cos = acc * winv; rowsum exp(64*cos - 64) ----
    float* racc = (float*)(smem + SM_W);   // stages are free now
    const int q  = lane & 3;
    const int g8 = lane >> 2;

    float2 wv[8];
    #pragma unroll
    for (int ni = 0; ni < 8; ++ni)
        wv[ni] = *(const float2*)&g_winv[c0 + wn * 64 + ni * 8 + 2 * q];

    #pragma unroll
    for (int mi = 0; mi < 4; ++mi) {
        #pragma unroll
        for (int h = 0; h < 2; ++h) {
            const int lrow = wm * 64 + mi * 16 + g8 + 8 * h;
            const int grow = mt * 128 + lrow;
            const int yv   = y[grow];
            float rs = 0.f;
            #pragma unroll
            for (int ni = 0; ni < 8; ++ni) {
                const int cb = c0 + wn * 64 + ni * 8 + 2 * q;
                float cv0 = acc[mi][ni][2 * h + 0] * wv[ni].x;
                float cv1 = acc[mi][ni][2 * h + 1] * wv[ni].y;
                if (cb == yv)     g_tgt[grow] = cv0;
                if (cb + 1 == yv) g_tgt[grow] = cv1;
                float e0 = __expf(fmaf(cv0, 64.f, -64.f));
                float e1 = __expf(fmaf(cv1, 64.f, -64.f));
                if (cb < NUM_C)     rs += e0;
                if (cb + 1 < NUM_C) rs += e1;
            }
            rs += __shfl_xor_sync(0xFFFFFFFFu, rs, 1);
            rs += __shfl_xor_sync(0xFFFFFFFFu, rs, 2);
            if (q == 0) racc[lrow * 4 + wn] = rs;
        }
    }
    __syncthreads();
    if (tid < 128) {
        float s = racc[tid * 4 + 0] + racc[tid * 4 + 1]
                + racc[tid * 4 + 2] + racc[tid * 4 + 3];
        g_partial[(size_t)cch * NB + mt * 128 + tid] = s;
    }
    #undef ISSUE_W
}

// ---------------------------------------------------------------------------
__global__ void k_final(float* __restrict__ out) {
    __shared__ float part[1024];
    __shared__ float red[NB];
    const int t    = threadIdx.x;
    const int row  = t >> 1;
    const int half = t & 1;
    const int cb   = half ? 196 : 0;
    const int ce   = half ? NCCH : 196;

    float s = 0.f;
    int c = cb;
    #pragma unroll 8
    for (; c + 8 <= ce; c += 8) {
        float a0 = g_partial[(size_t)(c + 0) * NB + row];
        float a1 = g_partial[(size_t)(c + 1) * NB + row];
        float a2 = g_partial[(size_t)(c + 2) * NB + row];
        float a3 = g_partial[(size_t)(c + 3) * NB + row];
        float a4 = g_partial[(size_t)(c + 4) * NB + row];
        float a5 = g_partial[(size_t)(c + 5) * NB + row];
        float a6 = g_partial[(size_t)(c + 6) * NB + row];
        float a7 = g_partial[(size_t)(c + 7) * NB + row];
        s += ((a0 + a1) + (a2 + a3)) + ((a4 + a5) + (a6 + a7));
    }
    for (; c < ce; ++c) s += g_partial[(size_t)c * NB + row];
    part[t] = s;
    __syncthreads();

    if (t < NB) {
        float S = part[2 * t] + part[2 * t + 1];
        float ct  = g_tgt[t];
        float sn  = sqrtf(fmaxf(1.f - ct * ct, 0.f));
        float cwm = ct * COS_M - sn * SIN_M;
        float phi = (ct > THv) ? cwm : (ct - MMRG);
        float Sp  = S - __expf(fmaf(ct, 64.f, -64.f)) + __expf(fmaf(phi, 64.f, -64.f));
        red[t] = 64.f + logf(Sp) - 64.f * phi;
    }
    __syncthreads();
    #pragma unroll
    for (int st = 256; st; st >>= 1) {
        if (t < st) red[t] += red[t + st];
        __syncthreads();
    }
    if (t == 0) out[0] = red[0] / (float)NB;
}

// ---------------------------------------------------------------------------
extern "C" void kernel_launch(void* const* d_in, const int* in_sizes, int n_in,
                              void* d_out, int out_size) {
    const float* x = (const float*)d_in[0];
    const int*   y = (const int*)d_in[1];
    const float* w = (const float*)d_in[2];
    float* out = (float*)d_out;

    cudaFuncSetAttribute(k_main, cudaFuncAttributeMaxDynamicSharedMemorySize,
                         (int)SMEM_BYTES);

    k_prep<<<CPAD / 128 + 2, 256>>>(x, w);
    k_main<<<dim3(4, NCCH), 256, SMEM_BYTES>>>(y);
    k_final<<<1, 1024>>>(out);
}

// round 4
// speedup vs baseline: 3.0564x; 1.0562x over previous
#include <cuda_runtime.h>
#include <cuda_bf16.h>
#include <cstdint>

// ---------------------------------------------------------------------------
// ArcFace loss on GB300 (sm_103a). tcgen05 rejected by compute_103 virtual
// target -> mma.sync pipeline.
//   k_prep  : W fp32 -> bf16 (g_wn) + inv-norms; X normalized -> bf16.
//             64 rows/block for latency hiding.
//   k_main  : 1564 CTAs (4 M-tiles x 391 chunks of 256 classes), 512 threads
//             (16 warps = 4/SMSP). X tile (128x512 bf16) smem-resident;
//             W 3-stage cp.async pipeline; 64x32 warp tiles, ldmatrix.x4 +
//             HMMA; fused exp(64*cos-64) row sums (fixed-max LSE).
//   k_final : combine partials, margin at target, CE, mean.
// ---------------------------------------------------------------------------

namespace {
constexpr int NUM_C = 100000;
constexpr int DIM   = 512;
constexpr int NB    = 512;

constexpr int NPC   = 256;                        // classes per CTA
constexpr int NCCH  = (NUM_C + NPC - 1) / NPC;    // 391
constexpr int CPAD  = NCCH * NPC;                 // 100096

constexpr int SM_X  = 0;                // 8 chunks * 16384 = 131072
constexpr int SM_W  = 131072;           // 3 stages * 32768 = 98304
constexpr size_t SMEM_BYTES = 229376;

constexpr float COS_M = 0.8775825618903728f;   // cos(0.5)
constexpr float SIN_M = 0.479425538604203f;    // sin(0.5)
constexpr float THv   = -0.8775825618903728f;  // -cos(m)
constexpr float MMRG  = 0.2397127693021015f;   // sin(m)*m
} // namespace

__device__ __align__(16) __nv_bfloat16 g_xn[NB * DIM];
__device__ __align__(16) __nv_bfloat16 g_wn[(size_t)CPAD * DIM];
__device__ float g_winv[CPAD];
__device__ float g_tgt[NB];
__device__ float g_partial[(size_t)NCCH * NB];

// ---------------------------------------------------------------------------
__device__ __forceinline__ uint32_t smem_u32(const void* p) {
    uint32_t a;
    asm("{ .reg .u64 t; cvta.to.shared.u64 t, %1; cvt.u32.u64 %0, t; }"
        : "=r"(a) : "l"(p));
    return a;
}
#define CP_ASYNC16(dst, src) \
    asm volatile("cp.async.cg.shared.global [%0], [%1], 16;" \
                 :: "r"(dst), "l"(src) : "memory")
#define CP_COMMIT() asm volatile("cp.async.commit_group;" ::: "memory")
#define CP_WAIT2()  asm volatile("cp.async.wait_group 2;" ::: "memory")

#define LDSM4(r, addr) \
    asm volatile("ldmatrix.sync.aligned.m8n8.x4.shared.b16 {%0,%1,%2,%3}, [%4];" \
                 : "=r"((r)[0]), "=r"((r)[1]), "=r"((r)[2]), "=r"((r)[3])        \
                 : "r"(addr))

__device__ __forceinline__ void mma16816(float* c, const uint32_t* a,
                                         const uint32_t* b) {
    asm volatile(
        "mma.sync.aligned.m16n8k16.row.col.f32.bf16.bf16.f32 "
        "{%0,%1,%2,%3}, {%4,%5,%6,%7}, {%8,%9}, {%0,%1,%2,%3};\n"
        : "+f"(c[0]), "+f"(c[1]), "+f"(c[2]), "+f"(c[3])
        : "r"(a[0]), "r"(a[1]), "r"(a[2]), "r"(a[3]), "r"(b[0]), "r"(b[1]));
}

// ---------------------------------------------------------------------------
// Prep: blocks 0..1563 convert W rows (64 each, zero-pad past NUM_C);
//       blocks 1564..1565 normalize X rows (256 each).
// ---------------------------------------------------------------------------
__global__ void k_prep(const float* __restrict__ x, const float* __restrict__ w) {
    const int bid  = blockIdx.x;
    const int wid  = threadIdx.x >> 5;
    const int lane = threadIdx.x & 31;

    if (bid < CPAD / 64) {
        const int base = bid * 64 + wid * 8;
        #pragma unroll
        for (int r = 0; r < 8; ++r) {
            const int row = base + r;
            float4 v[4];
            float ss = 0.f;
            if (row < NUM_C) {
                const float4* src = (const float4*)(w + (size_t)row * DIM);
                #pragma unroll
                for (int i = 0; i < 4; ++i) {
                    v[i] = src[lane + 32 * i];
                    ss += v[i].x * v[i].x + v[i].y * v[i].y
                        + v[i].z * v[i].z + v[i].w * v[i].w;
                }
            } else {
                #pragma unroll
                for (int i = 0; i < 4; ++i) v[i] = make_float4(0, 0, 0, 0);
            }
            #pragma unroll
            for (int o = 16; o; o >>= 1) ss += __shfl_xor_sync(0xFFFFFFFFu, ss, o);

            uint2* dst = (uint2*)(g_wn + (size_t)row * DIM);
            #pragma unroll
            for (int i = 0; i < 4; ++i) {
                __nv_bfloat162 lo = __floats2bfloat162_rn(v[i].x, v[i].y);
                __nv_bfloat162 hi = __floats2bfloat162_rn(v[i].z, v[i].w);
                uint2 u;
                u.x = *(uint32_t*)&lo;
                u.y = *(uint32_t*)&hi;
                dst[lane + 32 * i] = u;
            }
            if (lane == 0)
                g_winv[row] = (row < NUM_C) ? rsqrtf(fmaxf(ss, 1e-24f)) : 0.f;
        }
    } else {
        const int xb = (bid - CPAD / 64) * 256 + wid * 32;
        for (int r = 0; r < 32; ++r) {
            const int row = xb + r;
            const float4* xr = (const float4*)(x + (size_t)row * DIM);
            float4 v[4];
            float s = 0.f;
            #pragma unroll
            for (int j = 0; j < 4; ++j) {
                v[j] = xr[lane + 32 * j];
                s += v[j].x * v[j].x + v[j].y * v[j].y
                   + v[j].z * v[j].z + v[j].w * v[j].w;
            }
            #pragma unroll
            for (int o = 16; o; o >>= 1) s += __shfl_xor_sync(0xFFFFFFFFu, s, o);
            float inv = rsqrtf(fmaxf(s, 1e-24f));
            uint2* dst = (uint2*)(g_xn + (size_t)row * DIM);
            #pragma unroll
            for (int j = 0; j < 4; ++j) {
                __nv_bfloat162 lo = __floats2bfloat162_rn(v[j].x * inv, v[j].y * inv);
                __nv_bfloat162 hi = __floats2bfloat162_rn(v[j].z * inv, v[j].w * inv);
                uint2 u;
                u.x = *(uint32_t*)&lo;
                u.y = *(uint32_t*)&hi;
                dst[lane + 32 * j] = u;
            }
        }
    }
}

// ---------------------------------------------------------------------------
__global__ void __launch_bounds__(512, 1)
k_main(const int* __restrict__ y) {
    extern __shared__ char smem[];
    const uint32_t sb = smem_u32(smem);
    const int tid  = threadIdx.x;
    const int wid  = tid >> 5;
    const int lane = tid & 31;
    const int mt   = blockIdx.x;           // 0..3
    const int cch  = blockIdx.y;           // 0..390
    const int c0   = cch * NPC;
    const int wm   = wid >> 3;             // 0..1  (64-row half)
    const int wn   = wid & 7;              // 0..7  (32-col slice)

    // ---- prologue: X tile + W stages 0..2 ----
    {
        const char* xsrc = (const char*)g_xn + (size_t)mt * 128 * DIM * 2;
        #pragma unroll
        for (int i = 0; i < 16; ++i) {
            int li  = tid + 512 * i;
            int c   = li >> 10, lc = li & 1023;
            int row = lc >> 3, seg = lc & 7;
            uint32_t dst = sb + SM_X + c * 16384 + row * 128
                         + ((seg * 16) ^ ((row & 7) << 4));
            const char* src = xsrc + ((size_t)row * DIM + c * 64 + seg * 8) * 2;
            CP_ASYNC16(dst, src);
        }
    }
    const char* wbase = (const char*)g_wn + (size_t)c0 * DIM * 2;
    #define ISSUE_W(kc) do {                                                  \
        uint32_t stg = sb + SM_W + ((kc) % 3) * 32768;                        \
        _Pragma("unroll")                                                     \
        for (int i = 0; i < 4; ++i) {                                         \
            int li = tid + 512 * i;                                           \
            int row = li >> 3, seg = li & 7;                                  \
            uint32_t dst = stg + row * 128 + ((seg * 16) ^ ((row & 7) << 4)); \
            const char* src = wbase + ((size_t)row * DIM + (kc) * 64 + seg * 8) * 2; \
            CP_ASYNC16(dst, src);                                             \
        }                                                                     \
    } while (0)

    ISSUE_W(0); CP_COMMIT();
    ISSUE_W(1); CP_COMMIT();
    ISSUE_W(2); CP_COMMIT();

    float acc[4][4][4];
    #pragma unroll
    for (int mi = 0; mi < 4; ++mi)
        #pragma unroll
        for (int ni = 0; ni < 4; ++ni)
            #pragma unroll
            for (int j = 0; j < 4; ++j) acc[mi][ni][j] = 0.f;

    const uint32_t swz      = (lane & 7) << 4;
    const uint32_t xrowbase = (wm * 64 + (lane & 15)) * 128;
    const uint32_t kxA      = (lane >> 4) << 4;
    const uint32_t browbase = (wn * 32 + (lane & 7) + ((lane >> 4) << 3)) * 128;
    const uint32_t kxB      = ((lane >> 3) & 1) << 4;

    for (int kc = 0; kc < 8; ++kc) {
        CP_WAIT2();
        __syncthreads();
        const uint32_t xch = sb + SM_X + kc * 16384 + xrowbase;
        const uint32_t wst = sb + SM_W + (kc % 3) * 32768 + browbase;
        #pragma unroll
        for (int ks = 0; ks < 4; ++ks) {
            uint32_t a[4][4], bq[2][4];
            const uint32_t ka = (uint32_t)(ks * 32 + kxA) ^ swz;
            const uint32_t kb = (uint32_t)(ks * 32 + kxB) ^ swz;
            #pragma unroll
            for (int mi = 0; mi < 4; ++mi) LDSM4(a[mi], xch + mi * 2048 + ka);
            #pragma unroll
            for (int nb = 0; nb < 2; ++nb) LDSM4(bq[nb], wst + nb * 2048 + kb);
            #pragma unroll
            for (int mi = 0; mi < 4; ++mi)
                #pragma unroll
                for (int nb = 0; nb < 2; ++nb) {
                    mma16816(acc[mi][2 * nb],     a[mi], &bq[nb][0]);
                    mma16816(acc[mi][2 * nb + 1], a[mi], &bq[nb][2]);
                }
        }
        __syncthreads();
        if (kc < 5) ISSUE_W(kc + 3);
        CP_COMMIT();
    }

    // ---- epilogue: cos = acc * winv; rowsum exp(64*cos - 64) ----
    float* racc = (float*)(smem + SM_W);   // stages free now (128*8 floats)
    const int q  = lane & 3;
    const int g8 = lane >> 2;

    float2 wv[4];
    #pragma unroll
    for (int ni = 0; ni < 4; ++ni)
        wv[ni] = *(const float2*)&g_winv[c0 + wn * 32 + ni * 8 + 2 * q];

    #pragma unroll
    for (int mi = 0; mi < 4; ++mi) {
        #pragma unroll
        for (int h = 0; h < 2; ++h) {
            const int lrow = wm * 64 + mi * 16 + g8 + 8 * h;
            const int grow = mt * 128 + lrow;
            const int yv   = y[grow];
            float rs = 0.f;
            #pragma unroll
            for (int ni = 0; ni < 4; ++ni) {
                const int cb = c0 + wn * 32 + ni * 8 + 2 * q;
                float cv0 = acc[mi][ni][2 * h + 0] * wv[ni].x;
                float cv1 = acc[mi][ni][2 * h + 1] * wv[ni].y;
                if (cb == yv)     g_tgt[grow] = cv0;
                if (cb + 1 == yv) g_tgt[grow] = cv1;
                float e0 = __expf(fmaf(cv0, 64.f, -64.f));
                float e1 = __expf(fmaf(cv1, 64.f, -64.f));
                if (cb < NUM_C)     rs += e0;
                if (cb + 1 < NUM_C) rs += e1;
            }
            rs += __shfl_xor_sync(0xFFFFFFFFu, rs, 1);
            rs += __shfl_xor_sync(0xFFFFFFFFu, rs, 2);
            if (q == 0) racc[lrow * 8 + wn] = rs;
        }
    }
    __syncthreads();
    if (tid < 128) {
        float s = 0.f;
        #pragma unroll
        for (int k = 0; k < 8; ++k) s += racc[tid * 8 + k];
        g_partial[(size_t)cch * NB + mt * 128 + tid] = s;
    }
    #undef ISSUE_W
}

// ---------------------------------------------------------------------------
__global__ void k_final(float* __restrict__ out) {
    __shared__ float part[1024];
    __shared__ float red[NB];
    const int t    = threadIdx.x;
    const int row  = t >> 1;
    const int half = t & 1;
    const int cb   = half ? 196 : 0;
    const int ce   = half ? NCCH : 196;

    float s = 0.f;
    int c = cb;
    #pragma unroll 8
    for (; c + 8 <= ce; c += 8) {
        float a0 = g_partial[(size_t)(c + 0) * NB + row];
        float a1 = g_partial[(size_t)(c + 1) * NB + row];
        float a2 = g_partial[(size_t)(c + 2) * NB + row];
        float a3 = g_partial[(size_t)(c + 3) * NB + row];
        float a4 = g_partial[(size_t)(c + 4) * NB + row];
        float a5 = g_partial[(size_t)(c + 5) * NB + row];
        float a6 = g_partial[(size_t)(c + 6) * NB + row];
        float a7 = g_partial[(size_t)(c + 7) * NB + row];
        s += ((a0 + a1) + (a2 + a3)) + ((a4 + a5) + (a6 + a7));
    }
    for (; c < ce; ++c) s += g_partial[(size_t)c * NB + row];
    part[t] = s;
    __syncthreads();

    if (t < NB) {
        float S = part[2 * t] + part[2 * t + 1];
        float ct  = g_tgt[t];
        float sn  = sqrtf(fmaxf(1.f - ct * ct, 0.f));
        float cwm = ct * COS_M - sn * SIN_M;
        float phi = (ct > THv) ? cwm : (ct - MMRG);
        float Sp  = S - __expf(fmaf(ct, 64.f, -64.f)) + __expf(fmaf(phi, 64.f, -64.f));
        red[t] = 64.f + logf(Sp) - 64.f * phi;
    }
    __syncthreads();
    #pragma unroll
    for (int st = 256; st; st >>= 1) {
        if (t < st) red[t] += red[t + st];
        __syncthreads();
    }
    if (t == 0) out[0] = red[0] / (float)NB;
}

// ---------------------------------------------------------------------------
extern "C" void kernel_launch(void* const* d_in, const int* in_sizes, int n_in,
                              void* d_out, int out_size) {
    const float* x = (const float*)d_in[0];
    const int*   y = (const int*)d_in[1];
    const float* w = (const float*)d_in[2];
    float* out = (float*)d_out;

    cudaFuncSetAttribute(k_main, cudaFuncAttributeMaxDynamicSharedMemorySize,
                         (int)SMEM_BYTES);

    k_prep<<<CPAD / 64 + 2, 256>>>(x, w);
    k_main<<<dim3(4, NCCH), 512, SMEM_BYTES>>>(y);
    k_final<<<1, 1024>>>(out);
}